// round 1
// baseline (speedup 1.0000x reference)
#include <cuda_runtime.h>
#include <math.h>

#define NQ 6
#define NL 3
#define BK 32
#define SROW 68

// ---------------- precomputed tables ----------------
__device__ float2 g_U[NL][NQ][4];   // rotation matrices, row-major 2x2 complex
__device__ float  g_G[3][64];       // (Wf_B @ Wq) folded with Z-sign table
__device__ float  g_d[3];           // Wf_B @ bq + bf

// ---------------- f32x2 helpers ----------------
__device__ __forceinline__ unsigned long long pack2(float x, float y) {
    unsigned long long r;
    asm("mov.b64 %0, {%1, %2};" : "=l"(r) : "f"(x), "f"(y));
    return r;
}
__device__ __forceinline__ void unpack2(unsigned long long p, float& x, float& y) {
    asm("mov.b64 {%0, %1}, %2;" : "=f"(x), "=f"(y) : "l"(p));
}
__device__ __forceinline__ void ffma2(unsigned long long& d, unsigned long long a, unsigned long long b) {
    asm("fma.rn.f32x2 %0, %1, %2, %0;" : "+l"(d) : "l"(a), "l"(b));
}

// ---------------- kernel 0: tiny precompute ----------------
__global__ void precompute_kernel(const float* __restrict__ qw,
                                  const float* __restrict__ Wq,
                                  const float* __restrict__ bq,
                                  const float* __restrict__ Wf,
                                  const float* __restrict__ bf) {
    int t = threadIdx.x;  // 64 threads
    __shared__ float A[3][NQ];
    if (t < NL * NQ) {
        // rotation matrices: U = Rot(phi, theta, omega)
        float phi = qw[t * 3 + 0], th = qw[t * 3 + 1], om = qw[t * 3 + 2];
        float s2, c2;  sincosf(0.5f * th, &s2, &c2);
        float spo, cpo; sincosf(0.5f * (phi + om), &spo, &cpo);
        float smo, cmo; sincosf(0.5f * (phi - om), &smo, &cmo);
        int l = t / NQ, w = t % NQ;
        g_U[l][w][0] = make_float2( cpo * c2, -spo * c2);  // e^{-i(phi+om)/2} c
        g_U[l][w][1] = make_float2(-cmo * s2, -smo * s2);  // -e^{+i(phi-om)/2} s
        g_U[l][w][2] = make_float2( cmo * s2, -smo * s2);  // e^{-i(phi-om)/2} s
        g_U[l][w][3] = make_float2( cpo * c2,  spo * c2);  // e^{+i(phi+om)/2} c
    }
    if (t < 18) {  // A = Wf[:,64:80] @ Wq  (3 x 6)
        int j = t / 6, w = t % 6;
        float a = 0.f;
        for (int k = 0; k < 16; k++) a += Wf[j * 80 + 64 + k] * Wq[k * 6 + w];
        A[j][w] = a;
    }
    __syncthreads();
    for (int i = t; i < 192; i += blockDim.x) {
        int j = i >> 6, s = i & 63;
        float g = 0.f;
        #pragma unroll
        for (int w = 0; w < 6; w++)
            g += A[j][w] * (((s >> (5 - w)) & 1) ? -1.f : 1.f);
        g_G[j][s] = g;
    }
    if (t < 3) {
        float v = bf[t];
        for (int k = 0; k < 16; k++) v += Wf[t * 80 + 64 + k] * bq[k];
        g_d[t] = v;
    }
}

// ---------------- kernel 1: quantum simulation (writes out = partB) ----------------
__global__ __launch_bounds__(64) void quantum_kernel(const float* __restrict__ xq,
                                                     float* __restrict__ out, int B) {
    __shared__ float2 sU[NL * NQ][4];
    __shared__ float  sG[3][64];
    __shared__ float  sd[3];
    int t = threadIdx.x;
    for (int i = t; i < NL * NQ * 4; i += 64) (&sU[0][0])[i] = (&g_U[0][0][0])[i];
    for (int i = t; i < 192; i += 64)        (&sG[0][0])[i] = (&g_G[0][0])[i];
    if (t < 3) sd[t] = g_d[t];
    __syncthreads();

    int b = blockIdx.x * 64 + t;
    if (b >= B) return;

    float cs[NQ], sn[NQ];
    #pragma unroll
    for (int q = 0; q < NQ; q++) sincosf(0.5f * xq[b * NQ + q], &sn[q], &cs[q]);

    // initial product state (real); qubit q owns bit (5-q)
    float2 st[64];
    #pragma unroll
    for (int i = 0; i < 64; i++) {
        float p = 1.f;
        #pragma unroll
        for (int q = 0; q < NQ; q++) p *= ((i >> (5 - q)) & 1) ? sn[q] : cs[q];
        st[i] = make_float2(p, 0.f);
    }

    #pragma unroll
    for (int l = 0; l < NL; l++) {
        // single-qubit rotations
        #pragma unroll
        for (int w = 0; w < NQ; w++) {
            float2 u00 = sU[l * NQ + w][0], u01 = sU[l * NQ + w][1];
            float2 u10 = sU[l * NQ + w][2], u11 = sU[l * NQ + w][3];
            const int bit = 1 << (5 - w);
            #pragma unroll
            for (int i = 0; i < 64; i++) {
                if (i & bit) continue;
                const int j = i | bit;
                float2 a = st[i], c = st[j];
                st[i].x = u00.x * a.x - u00.y * a.y + u01.x * c.x - u01.y * c.y;
                st[i].y = u00.x * a.y + u00.y * a.x + u01.x * c.y + u01.y * c.x;
                st[j].x = u10.x * a.x - u10.y * a.y + u11.x * c.x - u11.y * c.y;
                st[j].y = u10.x * a.y + u10.y * a.x + u11.x * c.y + u11.y * c.x;
            }
        }
        // CNOT ring, offset r = l % 5 + 1, applied sequentially
        const int r = (l % (NQ - 1)) + 1;
        #pragma unroll
        for (int w = 0; w < NQ; w++) {
            const int tq = (w + r) % NQ;
            const int cbit = 1 << (5 - w);
            const int tbit = 1 << (5 - tq);
            #pragma unroll
            for (int i = 0; i < 64; i++) {
                if ((i & cbit) && !(i & tbit)) {
                    const int j = i | tbit;
                    float2 tmp = st[i]; st[i] = st[j]; st[j] = tmp;
                }
            }
        }
    }

    float o0 = sd[0], o1 = sd[1], o2 = sd[2];
    #pragma unroll
    for (int i = 0; i < 64; i++) {
        float p = st[i].x * st[i].x + st[i].y * st[i].y;
        o0 += p * sG[0][i];
        o1 += p * sG[1][i];
        o2 += p * sG[2][i];
    }
    out[(size_t)b * 3 + 0] = o0;
    out[(size_t)b * 3 + 1] = o1;
    out[(size_t)b * 3 + 2] = o2;
}

// ---------------- kernel 2: fused GEMM + relu + Wf reduction (out += partA) ----------------
// Block: 64 rows x 64 cols, 256 threads, 4x4 per thread, FFMA2 inner loop.
__global__ __launch_bounds__(256, 2) void gemm_kernel(const float* __restrict__ xc,
                                                      const float* __restrict__ W1,
                                                      const float* __restrict__ b1,
                                                      const float* __restrict__ Wf,
                                                      float* __restrict__ out) {
    __shared__ float As[2][BK][SROW];  // k-major: As[buf][k][row]
    __shared__ float Bs[2][BK][SROW];  // k-major: Bs[buf][k][col]
    __shared__ float red[64][3];

    const int tid = threadIdx.x;
    const int tx = tid & 15;          // col group (4 cols)
    const int ty = tid >> 4;          // row group (4 rows)
    const int row0 = blockIdx.x * 64;
    const int lr = tid >> 3;          // loader row 0..31
    const int lk = (tid & 7) << 2;    // loader k offset 0,4,..,28

    unsigned long long acc[4][2];
    #pragma unroll
    for (int r = 0; r < 4; r++) { acc[r][0] = 0ull; acc[r][1] = 0ull; }

    const float* xp = xc + (size_t)row0 * 2048;

    float4 pa[2], pb[2];
    #pragma unroll
    for (int p = 0; p < 2; p++) {
        const int r = lr + p * 32;
        pa[p] = *(const float4*)(xp + (size_t)r * 2048 + lk);
        pb[p] = *(const float4*)(W1 + (size_t)r * 2048 + lk);
    }
    #pragma unroll
    for (int p = 0; p < 2; p++) {
        const int r = lr + p * 32;
        As[0][lk + 0][r] = pa[p].x; As[0][lk + 1][r] = pa[p].y;
        As[0][lk + 2][r] = pa[p].z; As[0][lk + 3][r] = pa[p].w;
        Bs[0][lk + 0][r] = pb[p].x; Bs[0][lk + 1][r] = pb[p].y;
        Bs[0][lk + 2][r] = pb[p].z; Bs[0][lk + 3][r] = pb[p].w;
    }
    __syncthreads();

    for (int it = 0; it < 64; it++) {
        const int cur = it & 1;
        if (it < 63) {
            const int kg = (it + 1) * BK + lk;
            #pragma unroll
            for (int p = 0; p < 2; p++) {
                const int r = lr + p * 32;
                pa[p] = *(const float4*)(xp + (size_t)r * 2048 + kg);
                pb[p] = *(const float4*)(W1 + (size_t)r * 2048 + kg);
            }
        }
        #pragma unroll
        for (int k = 0; k < BK; k++) {
            const float4 av = *(const float4*)&As[cur][k][ty << 2];
            const float4 bv = *(const float4*)&Bs[cur][k][tx << 2];
            const unsigned long long b01 = pack2(bv.x, bv.y);
            const unsigned long long b23 = pack2(bv.z, bv.w);
            unsigned long long ar;
            ar = pack2(av.x, av.x); ffma2(acc[0][0], ar, b01); ffma2(acc[0][1], ar, b23);
            ar = pack2(av.y, av.y); ffma2(acc[1][0], ar, b01); ffma2(acc[1][1], ar, b23);
            ar = pack2(av.z, av.z); ffma2(acc[2][0], ar, b01); ffma2(acc[2][1], ar, b23);
            ar = pack2(av.w, av.w); ffma2(acc[3][0], ar, b01); ffma2(acc[3][1], ar, b23);
        }
        if (it < 63) {
            const int nxt = 1 - cur;
            #pragma unroll
            for (int p = 0; p < 2; p++) {
                const int r = lr + p * 32;
                As[nxt][lk + 0][r] = pa[p].x; As[nxt][lk + 1][r] = pa[p].y;
                As[nxt][lk + 2][r] = pa[p].z; As[nxt][lk + 3][r] = pa[p].w;
                Bs[nxt][lk + 0][r] = pb[p].x; Bs[nxt][lk + 1][r] = pb[p].y;
                Bs[nxt][lk + 2][r] = pb[p].z; Bs[nxt][lk + 3][r] = pb[p].w;
            }
        }
        __syncthreads();
    }

    // epilogue: bias + relu + 3-way Wf reduction within block
    for (int i = tid; i < 192; i += 256) (&red[0][0])[i] = 0.f;
    __syncthreads();

    float wf0[4], wf1[4], wf2[4], bb[4];
    #pragma unroll
    for (int c = 0; c < 4; c++) {
        const int col = (tx << 2) + c;
        wf0[c] = Wf[col];
        wf1[c] = Wf[80 + col];
        wf2[c] = Wf[160 + col];
        bb[c]  = b1[col];
    }
    #pragma unroll
    for (int r = 0; r < 4; r++) {
        float v[4];
        unpack2(acc[r][0], v[0], v[1]);
        unpack2(acc[r][1], v[2], v[3]);
        float p0 = 0.f, p1 = 0.f, p2 = 0.f;
        #pragma unroll
        for (int c = 0; c < 4; c++) {
            float cv = v[c] + bb[c];
            cv = cv > 0.f ? cv : 0.f;
            p0 += cv * wf0[c]; p1 += cv * wf1[c]; p2 += cv * wf2[c];
        }
        const int rr = (ty << 2) + r;
        atomicAdd(&red[rr][0], p0);
        atomicAdd(&red[rr][1], p1);
        atomicAdd(&red[rr][2], p2);
    }
    __syncthreads();
    for (int i = tid; i < 192; i += 256) {
        const int rr = i / 3, j = i - rr * 3;
        out[(size_t)(row0 + rr) * 3 + j] += red[rr][j];
    }
}

// ---------------- launch ----------------
extern "C" void kernel_launch(void* const* d_in, const int* in_sizes, int n_in,
                              void* d_out, int out_size) {
    const float* xc = (const float*)d_in[0];
    const float* xq = (const float*)d_in[1];
    const float* W1 = (const float*)d_in[2];
    const float* b1 = (const float*)d_in[3];
    const float* qw = (const float*)d_in[4];
    const float* Wq = (const float*)d_in[5];
    const float* bq = (const float*)d_in[6];
    const float* Wf = (const float*)d_in[7];
    const float* bf = (const float*)d_in[8];
    float* out = (float*)d_out;

    const int B = in_sizes[0] / 2048;  // 16384

    precompute_kernel<<<1, 64>>>(qw, Wq, bq, Wf, bf);
    quantum_kernel<<<B / 64, 64>>>(xq, out, B);
    gemm_kernel<<<B / 64, 256>>>(xc, W1, b1, Wf, out);
}

// round 3
// speedup vs baseline: 1.0393x; 1.0393x over previous
#include <cuda_runtime.h>
#include <math.h>

#define NQ 6
#define NL 3
#define BK 32
#define SROW 68

typedef unsigned long long ull;

// ---------------- f32x2 helpers ----------------
__device__ __forceinline__ ull pack2(float x, float y) {
    ull r;
    asm("mov.b64 %0, {%1, %2};" : "=l"(r) : "f"(x), "f"(y));
    return r;
}
__device__ __forceinline__ void unpack2(ull p, float& x, float& y) {
    asm("mov.b64 {%0, %1}, %2;" : "=f"(x), "=f"(y) : "l"(p));
}
__device__ __forceinline__ void ffma2(ull& d, ull a, ull b) {
    asm("fma.rn.f32x2 %0, %1, %2, %0;" : "+l"(d) : "l"(a), "l"(b));
}

// ---------------- kernel 1: quantum sim (self-contained, writes out = partB) ----------------
__global__ __launch_bounds__(128) void quantum_kernel(const float* __restrict__ xq,
                                                      const float* __restrict__ qw,
                                                      const float* __restrict__ Wq,
                                                      const float* __restrict__ bq,
                                                      const float* __restrict__ Wf,
                                                      const float* __restrict__ bf,
                                                      float* __restrict__ out, int B) {
    __shared__ float2 sU[NL * NQ][4];
    __shared__ float  sG[3][64];
    __shared__ float  sd[3];
    __shared__ float  sA[3][NQ];
    int t = threadIdx.x;

    // per-block precompute (cheap, removes serial precompute kernel)
    if (t < NL * NQ) {
        float phi = qw[t * 3 + 0], th = qw[t * 3 + 1], om = qw[t * 3 + 2];
        float s2, c2;  sincosf(0.5f * th, &s2, &c2);
        float spo, cpo; sincosf(0.5f * (phi + om), &spo, &cpo);
        float smo, cmo; sincosf(0.5f * (phi - om), &smo, &cmo);
        sU[t][0] = make_float2( cpo * c2, -spo * c2);
        sU[t][1] = make_float2(-cmo * s2, -smo * s2);
        sU[t][2] = make_float2( cmo * s2, -smo * s2);
        sU[t][3] = make_float2( cpo * c2,  spo * c2);
    }
    if (t >= 32 && t < 32 + 18) {  // A = Wf[:,64:80] @ Wq  (3 x 6)
        int u = t - 32;
        int j = u / 6, w = u % 6;
        float a = 0.f;
        for (int k = 0; k < 16; k++) a += Wf[j * 80 + 64 + k] * Wq[k * 6 + w];
        sA[j][w] = a;
    }
    __syncthreads();
    for (int i = t; i < 192; i += 128) {
        int j = i >> 6, s = i & 63;
        float g = 0.f;
        #pragma unroll
        for (int w = 0; w < 6; w++)
            g += sA[j][w] * (((s >> (5 - w)) & 1) ? -1.f : 1.f);
        sG[j][s] = g;
    }
    if (t < 3) {
        float v = bf[t];
        for (int k = 0; k < 16; k++) v += Wf[t * 80 + 64 + k] * bq[k];
        sd[t] = v;
    }
    __syncthreads();

    int b = blockIdx.x * 128 + t;
    if (b >= B) return;

    float cs[NQ], sn[NQ];
    #pragma unroll
    for (int q = 0; q < NQ; q++) sincosf(0.5f * xq[b * NQ + q], &sn[q], &cs[q]);

    // initial product state (real); qubit q owns bit (5-q)
    float2 st[64];
    #pragma unroll
    for (int i = 0; i < 64; i++) {
        float p = 1.f;
        #pragma unroll
        for (int q = 0; q < NQ; q++) p *= ((i >> (5 - q)) & 1) ? sn[q] : cs[q];
        st[i] = make_float2(p, 0.f);
    }

    #pragma unroll
    for (int l = 0; l < NL; l++) {
        #pragma unroll
        for (int w = 0; w < NQ; w++) {
            float2 u00 = sU[l * NQ + w][0], u01 = sU[l * NQ + w][1];
            float2 u10 = sU[l * NQ + w][2], u11 = sU[l * NQ + w][3];
            const int bit = 1 << (5 - w);
            #pragma unroll
            for (int i = 0; i < 64; i++) {
                if (i & bit) continue;
                const int j = i | bit;
                float2 a = st[i], c = st[j];
                st[i].x = u00.x * a.x - u00.y * a.y + u01.x * c.x - u01.y * c.y;
                st[i].y = u00.x * a.y + u00.y * a.x + u01.x * c.y + u01.y * c.x;
                st[j].x = u10.x * a.x - u10.y * a.y + u11.x * c.x - u11.y * c.y;
                st[j].y = u10.x * a.y + u10.y * a.x + u11.x * c.y + u11.y * c.x;
            }
        }
        const int r = (l % (NQ - 1)) + 1;
        #pragma unroll
        for (int w = 0; w < NQ; w++) {
            const int tq = (w + r) % NQ;
            const int cbit = 1 << (5 - w);
            const int tbit = 1 << (5 - tq);
            #pragma unroll
            for (int i = 0; i < 64; i++) {
                if ((i & cbit) && !(i & tbit)) {
                    const int j = i | tbit;
                    float2 tmp = st[i]; st[i] = st[j]; st[j] = tmp;
                }
            }
        }
    }

    float o0 = sd[0], o1 = sd[1], o2 = sd[2];
    #pragma unroll
    for (int i = 0; i < 64; i++) {
        float p = st[i].x * st[i].x + st[i].y * st[i].y;
        o0 += p * sG[0][i];
        o1 += p * sG[1][i];
        o2 += p * sG[2][i];
    }
    out[(size_t)b * 3 + 0] = o0;
    out[(size_t)b * 3 + 1] = o1;
    out[(size_t)b * 3 + 2] = o2;
}

// ---------------- kernel 2: fused GEMM + relu + Wf reduction (out += partA) ----------------
// 64x64 block tile, 128 threads (16 tx x 8 ty), 8x4 per thread.
// FFMA2 pairs over ROWS (free from ld.shared.v2.u64); only b needs 4 dups/k.
__global__ __launch_bounds__(128, 2) void gemm_kernel(const float* __restrict__ xc,
                                                      const float* __restrict__ W1,
                                                      const float* __restrict__ b1,
                                                      const float* __restrict__ Wf,
                                                      float* __restrict__ out) {
    __shared__ float As[2][BK][SROW];  // k-major: As[buf][k][row]
    __shared__ float Bs[2][BK][SROW];  // k-major: Bs[buf][k][col]

    const int tid = threadIdx.x;
    const int tx = tid & 15;           // col group: cols 4tx..4tx+3
    const int ty = tid >> 4;           // row group: rows 8ty..8ty+7
    const int row0 = blockIdx.x * 64;

    // loader: r = tid&63 (row for A / col for B), k-half = (tid>>6)*16
    const int lr = tid & 63;
    const int lk = (tid >> 6) << 4;
    const float* xp = xc + (size_t)(row0 + lr) * 2048 + lk;
    const float* wp = W1 + (size_t)lr * 2048 + lk;

    ull acc[4][4];
    #pragma unroll
    for (int i = 0; i < 4; i++)
        #pragma unroll
        for (int j = 0; j < 4; j++) acc[i][j] = 0ull;

    float4 pa[4], pb[4];
    #pragma unroll
    for (int j = 0; j < 4; j++) {
        pa[j] = *(const float4*)(xp + 4 * j);
        pb[j] = *(const float4*)(wp + 4 * j);
    }
    #pragma unroll
    for (int j = 0; j < 4; j++) {
        As[0][lk + 4 * j + 0][lr] = pa[j].x; As[0][lk + 4 * j + 1][lr] = pa[j].y;
        As[0][lk + 4 * j + 2][lr] = pa[j].z; As[0][lk + 4 * j + 3][lr] = pa[j].w;
        Bs[0][lk + 4 * j + 0][lr] = pb[j].x; Bs[0][lk + 4 * j + 1][lr] = pb[j].y;
        Bs[0][lk + 4 * j + 2][lr] = pb[j].z; Bs[0][lk + 4 * j + 3][lr] = pb[j].w;
    }
    __syncthreads();

    #pragma unroll 1
    for (int it = 0; it < 64; it++) {
        const int cur = it & 1;
        if (it < 63) {
            const int base = (it + 1) * BK;
            #pragma unroll
            for (int j = 0; j < 4; j++) {
                pa[j] = *(const float4*)(xp + base + 4 * j);
                pb[j] = *(const float4*)(wp + base + 4 * j);
            }
        }
        #pragma unroll
        for (int k = 0; k < BK; k++) {
            const ulonglong2 a01 = *(const ulonglong2*)&As[cur][k][ty << 3];
            const ulonglong2 a23 = *(const ulonglong2*)&As[cur][k][(ty << 3) + 4];
            const float4 bv = *(const float4*)&Bs[cur][k][tx << 2];
            const ull b0 = pack2(bv.x, bv.x);
            const ull b1d = pack2(bv.y, bv.y);
            const ull b2 = pack2(bv.z, bv.z);
            const ull b3 = pack2(bv.w, bv.w);
            ffma2(acc[0][0], a01.x, b0); ffma2(acc[0][1], a01.x, b1d);
            ffma2(acc[0][2], a01.x, b2); ffma2(acc[0][3], a01.x, b3);
            ffma2(acc[1][0], a01.y, b0); ffma2(acc[1][1], a01.y, b1d);
            ffma2(acc[1][2], a01.y, b2); ffma2(acc[1][3], a01.y, b3);
            ffma2(acc[2][0], a23.x, b0); ffma2(acc[2][1], a23.x, b1d);
            ffma2(acc[2][2], a23.x, b2); ffma2(acc[2][3], a23.x, b3);
            ffma2(acc[3][0], a23.y, b0); ffma2(acc[3][1], a23.y, b1d);
            ffma2(acc[3][2], a23.y, b2); ffma2(acc[3][3], a23.y, b3);
        }
        if (it < 63) {
            const int nxt = 1 - cur;
            #pragma unroll
            for (int j = 0; j < 4; j++) {
                As[nxt][lk + 4 * j + 0][lr] = pa[j].x; As[nxt][lk + 4 * j + 1][lr] = pa[j].y;
                As[nxt][lk + 4 * j + 2][lr] = pa[j].z; As[nxt][lk + 4 * j + 3][lr] = pa[j].w;
                Bs[nxt][lk + 4 * j + 0][lr] = pb[j].x; Bs[nxt][lk + 4 * j + 1][lr] = pb[j].y;
                Bs[nxt][lk + 4 * j + 2][lr] = pb[j].z; Bs[nxt][lk + 4 * j + 3][lr] = pb[j].w;
            }
        }
        __syncthreads();
    }

    // epilogue: stage C tile in smem (reuse As region: 2*32*68 = 4352 floats = 64*68)
    float* Cs = &As[0][0][0];
    #pragma unroll
    for (int rp = 0; rp < 4; rp++) {
        #pragma unroll
        for (int c = 0; c < 4; c++) {
            float vlo, vhi;
            unpack2(acc[rp][c], vlo, vhi);
            const int col = (tx << 2) + c;
            const int rlo = (ty << 3) + 2 * rp;
            Cs[rlo * SROW + col]       = vlo;
            Cs[(rlo + 1) * SROW + col] = vhi;
        }
    }
    __syncthreads();

    if (tid < 64) {
        const int row = tid;
        float o0 = 0.f, o1 = 0.f, o2 = 0.f;
        #pragma unroll 8
        for (int c = 0; c < 64; c++) {
            float cv = Cs[row * SROW + c] + b1[c];
            cv = cv > 0.f ? cv : 0.f;
            o0 += cv * Wf[c];
            o1 += cv * Wf[80 + c];
            o2 += cv * Wf[160 + c];
        }
        const size_t o = (size_t)(row0 + row) * 3;
        out[o + 0] += o0;
        out[o + 1] += o1;
        out[o + 2] += o2;
    }
}

// ---------------- launch ----------------
extern "C" void kernel_launch(void* const* d_in, const int* in_sizes, int n_in,
                              void* d_out, int out_size) {
    const float* xc = (const float*)d_in[0];
    const float* xq = (const float*)d_in[1];
    const float* W1 = (const float*)d_in[2];
    const float* b1 = (const float*)d_in[3];
    const float* qw = (const float*)d_in[4];
    const float* Wq = (const float*)d_in[5];
    const float* bq = (const float*)d_in[6];
    const float* Wf = (const float*)d_in[7];
    const float* bf = (const float*)d_in[8];
    float* out = (float*)d_out;

    const int B = in_sizes[0] / 2048;  // 16384

    quantum_kernel<<<B / 128, 128>>>(xq, qw, Wq, bq, Wf, bf, out, B);
    gemm_kernel<<<B / 64, 128>>>(xc, W1, b1, Wf, out);
}

// round 5
// speedup vs baseline: 2.3505x; 2.2617x over previous
#include <cuda_runtime.h>
#include <math.h>
#include <stdint.h>

#define NQ 6
#define NL 3

typedef uint32_t u32;

// ==================== quantum tables ====================
__device__ float g_Gr[64][64];
__device__ float g_Gi[64][64];
__device__ float g_G[3][64];
__device__ float g_d[3];

// ---- kernel 0: build full 64x64 evolution matrix + folded tables ----
__global__ __launch_bounds__(256) void precompute_kernel(const float* __restrict__ qw,
                                                         const float* __restrict__ Wq,
                                                         const float* __restrict__ bq,
                                                         const float* __restrict__ Wf,
                                                         const float* __restrict__ bf) {
    __shared__ float Mr[64][64];
    __shared__ float Mi[64][64];
    __shared__ float2 sU[NL * NQ][4];
    __shared__ float sA[3][NQ];
    const int t = threadIdx.x;

    if (t < NL * NQ) {
        float phi = qw[t * 3 + 0], th = qw[t * 3 + 1], om = qw[t * 3 + 2];
        float s2, c2;  sincosf(0.5f * th, &s2, &c2);
        float spo, cpo; sincosf(0.5f * (phi + om), &spo, &cpo);
        float smo, cmo; sincosf(0.5f * (phi - om), &smo, &cmo);
        sU[t][0] = make_float2( cpo * c2, -spo * c2);
        sU[t][1] = make_float2(-cmo * s2, -smo * s2);
        sU[t][2] = make_float2( cmo * s2, -smo * s2);
        sU[t][3] = make_float2( cpo * c2,  spo * c2);
    }
    if (t >= 32 && t < 50) {
        int u = t - 32, j = u / 6, w = u % 6;
        float a = 0.f;
        for (int k = 0; k < 16; k++) a += Wf[j * 80 + 64 + k] * Wq[k * 6 + w];
        sA[j][w] = a;
    }
    for (int idx = t; idx < 4096; idx += 256) {
        int r = idx >> 6, c = idx & 63;
        Mr[r][c] = (r == c) ? 1.f : 0.f;
        Mi[r][c] = 0.f;
    }
    __syncthreads();

    for (int l = 0; l < NL; l++) {
        for (int w = 0; w < NQ; w++) {
            float2 u00 = sU[l * NQ + w][0], u01 = sU[l * NQ + w][1];
            float2 u10 = sU[l * NQ + w][2], u11 = sU[l * NQ + w][3];
            const int bit = 1 << (5 - w);
            for (int v = t; v < 2048; v += 256) {
                int p = v >> 6, c = v & 63;
                int i = ((p & ~(bit - 1)) << 1) | (p & (bit - 1));
                int j = i | bit;
                float ar = Mr[i][c], ai = Mi[i][c], br = Mr[j][c], bi = Mi[j][c];
                Mr[i][c] = u00.x * ar - u00.y * ai + u01.x * br - u01.y * bi;
                Mi[i][c] = u00.x * ai + u00.y * ar + u01.x * bi + u01.y * br;
                Mr[j][c] = u10.x * ar - u10.y * ai + u11.x * br - u11.y * bi;
                Mi[j][c] = u10.x * ai + u10.y * ar + u11.x * bi + u11.y * br;
            }
            __syncthreads();
        }
        const int r = (l % (NQ - 1)) + 1;
        for (int w = 0; w < NQ; w++) {
            const int tq = (w + r) % NQ;
            const int cbit = 1 << (5 - w);
            const int tbit = 1 << (5 - tq);
            const int lo_b = cbit < tbit ? cbit : tbit;
            const int hi_b = cbit < tbit ? tbit : cbit;
            for (int v = t; v < 1024; v += 256) {
                int x = v >> 6, c = v & 63;
                int t1 = ((x & ~(lo_b - 1)) << 1) | (x & (lo_b - 1));
                int i0 = ((t1 & ~(hi_b - 1)) << 1) | (t1 & (hi_b - 1));
                int i = i0 | cbit;
                int j = i | tbit;
                float tr = Mr[i][c]; Mr[i][c] = Mr[j][c]; Mr[j][c] = tr;
                float ti = Mi[i][c]; Mi[i][c] = Mi[j][c]; Mi[j][c] = ti;
            }
            __syncthreads();
        }
    }

    for (int idx = t; idx < 4096; idx += 256) {
        int r = idx >> 6, c = idx & 63;
        g_Gr[r][c] = Mr[r][c];
        g_Gi[r][c] = Mi[r][c];
    }
    for (int i = t; i < 192; i += 256) {
        int j = i >> 6, s = i & 63;
        float g = 0.f;
        #pragma unroll
        for (int w = 0; w < 6; w++)
            g += sA[j][w] * (((s >> (5 - w)) & 1) ? -1.f : 1.f);
        g_G[j][s] = g;
    }
    if (t < 3) {
        float v = bf[t];
        for (int k = 0; k < 16; k++) v += Wf[t * 80 + 64 + k] * bq[k];
        g_d[t] = v;
    }
}

// ---- kernel 1: quantum matvec (writes out = partB) ----
__global__ __launch_bounds__(128, 1) void quantum_kernel(const float* __restrict__ xq,
                                                         float* __restrict__ out, int B) {
    __shared__ float sGr[64][64];
    __shared__ float sGi[64][64];
    __shared__ float sG[3][64];
    __shared__ float sd[3];
    const int t = threadIdx.x;

    for (int idx = t; idx < 4096; idx += 128) {
        int r = idx >> 6, c = idx & 63;
        sGr[r][c] = g_Gr[r][c];
        sGi[r][c] = g_Gi[r][c];
    }
    for (int i = t; i < 192; i += 128) sG[i >> 6][i & 63] = g_G[i >> 6][i & 63];
    if (t < 3) sd[t] = g_d[t];
    __syncthreads();

    const int b = blockIdx.x * 128 + t;
    if (b >= B) return;

    float cs[NQ], sn[NQ];
    #pragma unroll
    for (int q = 0; q < NQ; q++) sincosf(0.5f * xq[b * NQ + q], &sn[q], &cs[q]);

    // psi0 (real); qubit q owns bit (5-q)
    float a[64];
    a[0] = cs[0]; a[1] = sn[0];
    #pragma unroll
    for (int q = 1; q < NQ; q++) {
        const int n = 1 << q;
        #pragma unroll 32
        for (int j = n - 1; j >= 0; j--) {
            float v = a[j];
            a[2 * j]     = v * cs[q];
            a[2 * j + 1] = v * sn[q];
        }
    }

    float o0 = sd[0], o1 = sd[1], o2 = sd[2];
    #pragma unroll 2
    for (int s = 0; s < 64; s++) {
        const float4* gr = (const float4*)sGr[s];
        const float4* gi = (const float4*)sGi[s];
        float yr0 = 0.f, yr1 = 0.f, yi0 = 0.f, yi1 = 0.f;
        #pragma unroll
        for (int t4 = 0; t4 < 16; t4++) {
            float4 g1 = gr[t4], g2 = gi[t4];
            const float* av = &a[t4 * 4];
            yr0 += g1.x * av[0]; yr1 += g1.y * av[1];
            yr0 += g1.z * av[2]; yr1 += g1.w * av[3];
            yi0 += g2.x * av[0]; yi1 += g2.y * av[1];
            yi0 += g2.z * av[2]; yi1 += g2.w * av[3];
        }
        float yr = yr0 + yr1, yi = yi0 + yi1;
        float p = yr * yr + yi * yi;
        o0 += p * sG[0][s];
        o1 += p * sG[1][s];
        o2 += p * sG[2][s];
    }
    const size_t o = (size_t)b * 3;
    out[o + 0] = o0;
    out[o + 1] = o1;
    out[o + 2] = o2;
}

// ==================== GEMM: mma.sync bf16-split ====================
// CTA: 128 thr (4 warps), tile 64 rows x 64 cols, K-chunk 32, 3-buffer smem ring.
#define KC 32
#define NCHUNK 64
#define BUF_A_HI 0
#define BUF_A_LO 4096
#define BUF_B_HI 8192
#define BUF_B_LO 12288
#define BUFSZ 16384
#define GEMM_DSMEM (3 * BUFSZ + 1024)

__device__ __forceinline__ u32 smem_u32(const void* p) {
    u32 a;
    asm("{ .reg .u64 t; cvta.to.shared.u64 t, %1; cvt.u32.u64 %0, t; }" : "=r"(a) : "l"(p));
    return a;
}

// XOR-swizzled offset for a [rows][KC] bf16 tile packed 2 rows per 128B line.
__device__ __forceinline__ u32 aoff(u32 row, u32 k) {
    u32 o = ((row >> 1) << 7) | ((row & 1) << 6) | (k << 1);
    return o ^ (((row >> 1) & 7) << 4);
}

#define LDMX4(r0, r1, r2, r3, addr) \
    asm volatile("ldmatrix.sync.aligned.m8n8.x4.shared.b16 {%0,%1,%2,%3}, [%4];" \
        : "=r"(r0), "=r"(r1), "=r"(r2), "=r"(r3) : "r"(addr))

#define MMA16816(d, a, b0, b1) \
    asm volatile("mma.sync.aligned.m16n8k16.row.col.f32.bf16.bf16.f32 " \
        "{%0,%1,%2,%3}, {%4,%5,%6,%7}, {%8,%9}, {%0,%1,%2,%3};" \
        : "+f"((d)[0]), "+f"((d)[1]), "+f"((d)[2]), "+f"((d)[3]) \
        : "r"((a)[0]), "r"((a)[1]), "r"((a)[2]), "r"((a)[3]), "r"(b0), "r"(b1))

// split one float4 into bf16-hi pair-words and bf16-lo pair-words, store 8B each
__device__ __forceinline__ void split4(u32 hi_addr, u32 lo_addr, float4 v) {
    u32 b0 = __float_as_uint(v.x), b1 = __float_as_uint(v.y);
    u32 b2 = __float_as_uint(v.z), b3 = __float_as_uint(v.w);
    u32 h01 = __byte_perm(b0, b1, 0x7632);
    u32 h23 = __byte_perm(b2, b3, 0x7632);
    float l0 = v.x - __uint_as_float(b0 & 0xFFFF0000u);
    float l1 = v.y - __uint_as_float(b1 & 0xFFFF0000u);
    float l2 = v.z - __uint_as_float(b2 & 0xFFFF0000u);
    float l3 = v.w - __uint_as_float(b3 & 0xFFFF0000u);
    u32 L01, L23;
    asm("cvt.rn.bf16x2.f32 %0, %1, %2;" : "=r"(L01) : "f"(l1), "f"(l0));
    asm("cvt.rn.bf16x2.f32 %0, %1, %2;" : "=r"(L23) : "f"(l3), "f"(l2));
    asm volatile("st.shared.v2.b32 [%0], {%1,%2};" :: "r"(hi_addr), "r"(h01), "r"(h23) : "memory");
    asm volatile("st.shared.v2.b32 [%0], {%1,%2};" :: "r"(lo_addr), "r"(L01), "r"(L23) : "memory");
}

__global__ __launch_bounds__(128, 2) void gemm_kernel(const float* __restrict__ xc,
                                                      const float* __restrict__ W1,
                                                      const float* __restrict__ b1,
                                                      const float* __restrict__ Wf,
                                                      float* __restrict__ out) {
    extern __shared__ char dyn_smem[];
    __shared__ float sWf[3][64];
    __shared__ float sB1[64];

    const u32 sbase = (smem_u32(dyn_smem) + 1023u) & ~1023u;
    const int tid = threadIdx.x;
    const int lane = tid & 31;
    const int warp = tid >> 5;
    const int row0 = blockIdx.x * 64;
    const int m0 = warp * 16;

    if (tid < 64) sB1[tid] = b1[tid];
    if (tid >= 64) {
        int u = tid - 64;
        sWf[0][u] = Wf[u];
        sWf[1][u] = Wf[80 + u];
        sWf[2][u] = Wf[160 + u];
    }

    // loader coords: 512 float4 per matrix per chunk, 4 per thread
    int lrow[4], lk[4];
    #pragma unroll
    for (int g = 0; g < 4; g++) {
        int f = g * 128 + tid;
        lrow[g] = f >> 3;
        lk[g] = (f & 7) * 4;
    }

    float4 pa[4], pb[4];
    float acc[8][4];
    #pragma unroll
    for (int nt = 0; nt < 8; nt++)
        #pragma unroll
        for (int e = 0; e < 4; e++) acc[nt][e] = 0.f;

    // a-frag / b-frag ldmatrix address components (fixed per thread)
    const u32 arow = (u32)(m0 + (lane & 7) + ((lane >> 3) & 1) * 8);
    const u32 akof = (u32)((lane >> 4) * 8);
    const u32 brow_base = (u32)((lane & 7) + (lane >> 4) * 8);
    const u32 bkof = (u32)(((lane >> 3) & 1) * 8);

#define LOAD_CHUNK(kc) do { \
    _Pragma("unroll") \
    for (int g = 0; g < 4; g++) { \
        pa[g] = *(const float4*)(xc + (size_t)(row0 + lrow[g]) * 2048 + (kc) + lk[g]); \
        pb[g] = *(const float4*)(W1 + (size_t)lrow[g] * 2048 + (kc) + lk[g]); \
    } } while (0)

#define STORE_CHUNK(bufb) do { \
    _Pragma("unroll") \
    for (int g = 0; g < 4; g++) { \
        u32 o = aoff((u32)lrow[g], (u32)lk[g]); \
        split4((bufb) + BUF_A_HI + o, (bufb) + BUF_A_LO + o, pa[g]); \
        split4((bufb) + BUF_B_HI + o, (bufb) + BUF_B_LO + o, pb[g]); \
    } } while (0)

    // prologue: fill buffers 0,1; prefetch chunk 2
    LOAD_CHUNK(0);
    STORE_CHUNK(sbase);
    LOAD_CHUNK(KC);
    STORE_CHUNK(sbase + BUFSZ);
    LOAD_CHUNK(2 * KC);
    __syncthreads();

    #pragma unroll 1
    for (int i = 0; i < NCHUNK; i++) {
        // store chunk i+2 (regs) into ring slot (i+2)%3
        if (i + 2 < NCHUNK) {
            STORE_CHUNK(sbase + ((i + 2) % 3) * BUFSZ);
        }
        // prefetch chunk i+3
        if (i + 3 < NCHUNK) {
            LOAD_CHUNK((i + 3) * KC);
        }
        // mma on chunk i
        const u32 bb = sbase + (i % 3) * BUFSZ;
        #pragma unroll
        for (int ks = 0; ks < 2; ks++) {
            u32 ah[4], al[4];
            u32 aaddr = aoff(arow, (u32)(ks * 16) + akof);
            LDMX4(ah[0], ah[1], ah[2], ah[3], bb + BUF_A_HI + aaddr);
            LDMX4(al[0], al[1], al[2], al[3], bb + BUF_A_LO + aaddr);
            u32 bh[16], bl[16];
            #pragma unroll
            for (int g = 0; g < 4; g++) {
                u32 baddr = aoff((u32)(g * 16) + brow_base, (u32)(ks * 16) + bkof);
                LDMX4(bh[4 * g], bh[4 * g + 1], bh[4 * g + 2], bh[4 * g + 3], bb + BUF_B_HI + baddr);
                LDMX4(bl[4 * g], bl[4 * g + 1], bl[4 * g + 2], bl[4 * g + 3], bb + BUF_B_LO + baddr);
            }
            #pragma unroll
            for (int nt = 0; nt < 8; nt++) {
                MMA16816(acc[nt], ah, bh[2 * nt], bh[2 * nt + 1]);
                MMA16816(acc[nt], ah, bl[2 * nt], bl[2 * nt + 1]);
                MMA16816(acc[nt], al, bh[2 * nt], bh[2 * nt + 1]);
            }
        }
        __syncthreads();
    }

    // epilogue: relu(acc + b1) . Wf, reduce over 4-lane column group
    float o[2][3] = {{0.f, 0.f, 0.f}, {0.f, 0.f, 0.f}};
    #pragma unroll
    for (int nt = 0; nt < 8; nt++) {
        const int n0 = nt * 8 + 2 * (lane & 3);
        const int n1 = n0 + 1;
        const float bb0 = sB1[n0], bb1 = sB1[n1];
        float c00 = acc[nt][0] + bb0; c00 = c00 > 0.f ? c00 : 0.f;
        float c01 = acc[nt][1] + bb1; c01 = c01 > 0.f ? c01 : 0.f;
        float c10 = acc[nt][2] + bb0; c10 = c10 > 0.f ? c10 : 0.f;
        float c11 = acc[nt][3] + bb1; c11 = c11 > 0.f ? c11 : 0.f;
        #pragma unroll
        for (int j = 0; j < 3; j++) {
            o[0][j] += c00 * sWf[j][n0] + c01 * sWf[j][n1];
            o[1][j] += c10 * sWf[j][n0] + c11 * sWf[j][n1];
        }
    }
    #pragma unroll
    for (int r = 0; r < 2; r++)
        #pragma unroll
        for (int j = 0; j < 3; j++) {
            o[r][j] += __shfl_xor_sync(0xFFFFFFFFu, o[r][j], 1);
            o[r][j] += __shfl_xor_sync(0xFFFFFFFFu, o[r][j], 2);
        }
    if ((lane & 3) == 0) {
        const int gr0 = row0 + m0 + (lane >> 2);
        #pragma unroll
        for (int j = 0; j < 3; j++) {
            out[(size_t)gr0 * 3 + j]       += o[0][j];
            out[(size_t)(gr0 + 8) * 3 + j] += o[1][j];
        }
    }
}

// ==================== launch ====================
extern "C" void kernel_launch(void* const* d_in, const int* in_sizes, int n_in,
                              void* d_out, int out_size) {
    const float* xc = (const float*)d_in[0];
    const float* xq = (const float*)d_in[1];
    const float* W1 = (const float*)d_in[2];
    const float* b1 = (const float*)d_in[3];
    const float* qw = (const float*)d_in[4];
    const float* Wq = (const float*)d_in[5];
    const float* bq = (const float*)d_in[6];
    const float* Wf = (const float*)d_in[7];
    const float* bf = (const float*)d_in[8];
    float* out = (float*)d_out;

    const int B = in_sizes[0] / 2048;  // 16384

    static int configured = 0;
    if (!configured) {
        cudaFuncSetAttribute(gemm_kernel, cudaFuncAttributeMaxDynamicSharedMemorySize, GEMM_DSMEM);
        configured = 1;
    }

    precompute_kernel<<<1, 256>>>(qw, Wq, bq, Wf, bf);
    quantum_kernel<<<(B + 127) / 128, 128>>>(xq, out, B);
    gemm_kernel<<<B / 64, 128, GEMM_DSMEM>>>(xc, W1, b1, Wf, out);
}

// round 6
// speedup vs baseline: 2.4296x; 1.0336x over previous
#include <cuda_runtime.h>
#include <math.h>
#include <stdint.h>

#define NQ 6
#define NL 3

typedef uint32_t u32;

// ==================== quantum tables ====================
__device__ float g_Gr[64][64];
__device__ float g_Gi[64][64];
__device__ float g_G[3][64];
__device__ float g_d[3];

// ---- kernel 0: build 64x64 evolution matrix (4 blocks x 16 columns) ----
__global__ __launch_bounds__(256) void precompute_kernel(const float* __restrict__ qw,
                                                         const float* __restrict__ Wq,
                                                         const float* __restrict__ bq,
                                                         const float* __restrict__ Wf,
                                                         const float* __restrict__ bf) {
    __shared__ float Mr[64][17];
    __shared__ float Mi[64][17];
    __shared__ float2 sU[NL * NQ][4];
    __shared__ float sA[3][NQ];
    const int t = threadIdx.x;
    const int col0 = blockIdx.x * 16;

    if (t < NL * NQ) {
        float phi = qw[t * 3 + 0], th = qw[t * 3 + 1], om = qw[t * 3 + 2];
        float s2, c2;  sincosf(0.5f * th, &s2, &c2);
        float spo, cpo; sincosf(0.5f * (phi + om), &spo, &cpo);
        float smo, cmo; sincosf(0.5f * (phi - om), &smo, &cmo);
        sU[t][0] = make_float2( cpo * c2, -spo * c2);
        sU[t][1] = make_float2(-cmo * s2, -smo * s2);
        sU[t][2] = make_float2( cmo * s2, -smo * s2);
        sU[t][3] = make_float2( cpo * c2,  spo * c2);
    }
    if (blockIdx.x == 0 && t >= 32 && t < 50) {
        int u = t - 32, j = u / 6, w = u % 6;
        float a = 0.f;
        for (int k = 0; k < 16; k++) a += Wf[j * 80 + 64 + k] * Wq[k * 6 + w];
        sA[j][w] = a;
    }
    for (int idx = t; idx < 1024; idx += 256) {
        int r = idx >> 4, c = idx & 15;
        Mr[r][c] = (r == col0 + c) ? 1.f : 0.f;
        Mi[r][c] = 0.f;
    }
    __syncthreads();

    for (int l = 0; l < NL; l++) {
        for (int w = 0; w < NQ; w++) {
            float2 u00 = sU[l * NQ + w][0], u01 = sU[l * NQ + w][1];
            float2 u10 = sU[l * NQ + w][2], u11 = sU[l * NQ + w][3];
            const int bit = 1 << (5 - w);
            for (int v = t; v < 512; v += 256) {
                int p = v >> 4, c = v & 15;
                int i = ((p & ~(bit - 1)) << 1) | (p & (bit - 1));
                int j = i | bit;
                float ar = Mr[i][c], ai = Mi[i][c], br = Mr[j][c], bi = Mi[j][c];
                Mr[i][c] = u00.x * ar - u00.y * ai + u01.x * br - u01.y * bi;
                Mi[i][c] = u00.x * ai + u00.y * ar + u01.x * bi + u01.y * br;
                Mr[j][c] = u10.x * ar - u10.y * ai + u11.x * br - u11.y * bi;
                Mi[j][c] = u10.x * ai + u10.y * ar + u11.x * bi + u11.y * br;
            }
            __syncthreads();
        }
        const int r = (l % (NQ - 1)) + 1;
        for (int w = 0; w < NQ; w++) {
            const int tq = (w + r) % NQ;
            const int cbit = 1 << (5 - w);
            const int tbit = 1 << (5 - tq);
            const int lo_b = cbit < tbit ? cbit : tbit;
            const int hi_b = cbit < tbit ? tbit : cbit;
            for (int v = t; v < 256; v += 256) {
                int x = v >> 4, c = v & 15;
                int t1 = ((x & ~(lo_b - 1)) << 1) | (x & (lo_b - 1));
                int i0 = ((t1 & ~(hi_b - 1)) << 1) | (t1 & (hi_b - 1));
                int i = i0 | cbit;
                int j = i | tbit;
                float tr = Mr[i][c]; Mr[i][c] = Mr[j][c]; Mr[j][c] = tr;
                float ti = Mi[i][c]; Mi[i][c] = Mi[j][c]; Mi[j][c] = ti;
            }
            __syncthreads();
        }
    }

    for (int idx = t; idx < 1024; idx += 256) {
        int r = idx >> 4, c = idx & 15;
        g_Gr[r][col0 + c] = Mr[r][c];
        g_Gi[r][col0 + c] = Mi[r][c];
    }
    if (blockIdx.x == 0) {
        for (int i = t; i < 192; i += 256) {
            int j = i >> 6, s = i & 63;
            float g = 0.f;
            #pragma unroll
            for (int w = 0; w < 6; w++)
                g += sA[j][w] * (((s >> (5 - w)) & 1) ? -1.f : 1.f);
            g_G[j][s] = g;
        }
        if (t < 3) {
            float v = bf[t];
            for (int k = 0; k < 16; k++) v += Wf[t * 80 + 64 + k] * bq[k];
            g_d[t] = v;
        }
    }
}

// ==================== fused GEMM (mma.sync bf16-split) + quantum epilogue ====================
#define KC 32
#define NCHUNK 64
#define BUF_A_HI 0
#define BUF_A_LO 4096
#define BUF_B_HI 8192
#define BUF_B_LO 12288
#define BUFSZ 16384
#define RING (3 * BUFSZ)
// dynamic smem: 1024 align slack + ring 49152 + tables 35344
#define TABLES_BYTES (4096*4 + 4096*4 + 192*4 + 192*4 + 64*4 + 4*4 + 192*4)
#define GEMM_DSMEM (1024 + RING + TABLES_BYTES)

__device__ __forceinline__ u32 smem_u32(const void* p) {
    u32 a;
    asm("{ .reg .u64 t; cvta.to.shared.u64 t, %1; cvt.u32.u64 %0, t; }" : "=r"(a) : "l"(p));
    return a;
}

// XOR-swizzled offset for a [rows][KC] bf16 tile packed 2 rows per 128B line.
__device__ __forceinline__ u32 aoff(u32 row, u32 k) {
    u32 o = ((row >> 1) << 7) | ((row & 1) << 6) | (k << 1);
    return o ^ (((row >> 1) & 7) << 4);
}

#define LDMX4(r0, r1, r2, r3, addr) \
    asm volatile("ldmatrix.sync.aligned.m8n8.x4.shared.b16 {%0,%1,%2,%3}, [%4];" \
        : "=r"(r0), "=r"(r1), "=r"(r2), "=r"(r3) : "r"(addr))

#define MMA16816(d, a, b0, b1) \
    asm volatile("mma.sync.aligned.m16n8k16.row.col.f32.bf16.bf16.f32 " \
        "{%0,%1,%2,%3}, {%4,%5,%6,%7}, {%8,%9}, {%0,%1,%2,%3};" \
        : "+f"((d)[0]), "+f"((d)[1]), "+f"((d)[2]), "+f"((d)[3]) \
        : "r"((a)[0]), "r"((a)[1]), "r"((a)[2]), "r"((a)[3]), "r"(b0), "r"(b1))

__device__ __forceinline__ void split4(u32 hi_addr, u32 lo_addr, float4 v) {
    u32 b0 = __float_as_uint(v.x), b1 = __float_as_uint(v.y);
    u32 b2 = __float_as_uint(v.z), b3 = __float_as_uint(v.w);
    u32 h01 = __byte_perm(b0, b1, 0x7632);
    u32 h23 = __byte_perm(b2, b3, 0x7632);
    float l0 = v.x - __uint_as_float(b0 & 0xFFFF0000u);
    float l1 = v.y - __uint_as_float(b1 & 0xFFFF0000u);
    float l2 = v.z - __uint_as_float(b2 & 0xFFFF0000u);
    float l3 = v.w - __uint_as_float(b3 & 0xFFFF0000u);
    u32 L01, L23;
    asm("cvt.rn.bf16x2.f32 %0, %1, %2;" : "=r"(L01) : "f"(l1), "f"(l0));
    asm("cvt.rn.bf16x2.f32 %0, %1, %2;" : "=r"(L23) : "f"(l3), "f"(l2));
    asm volatile("st.shared.v2.b32 [%0], {%1,%2};" :: "r"(hi_addr), "r"(h01), "r"(h23) : "memory");
    asm volatile("st.shared.v2.b32 [%0], {%1,%2};" :: "r"(lo_addr), "r"(L01), "r"(L23) : "memory");
}

__global__ __launch_bounds__(128, 2) void fused_kernel(const float* __restrict__ xc,
                                                       const float* __restrict__ W1,
                                                       const float* __restrict__ b1,
                                                       const float* __restrict__ Wf,
                                                       const float* __restrict__ xq,
                                                       float* __restrict__ out) {
    extern __shared__ char dyn_smem[];

    const u32 sb = smem_u32(dyn_smem);
    const u32 ring = (sb + 1023u) & ~1023u;
    char* dbase = dyn_smem + (ring - sb);
    float* sGr = (float*)(dbase + RING);   // [64][64]
    float* sGi = sGr + 4096;               // [64][64]
    float* sG  = sGi + 4096;               // [3][64] flat
    float* sWf = sG + 192;                 // [3][64] flat
    float* sB1 = sWf + 192;                // [64]
    float* sd  = sB1 + 64;                 // [3] (pad 4)
    float* sQ  = sd + 4;                   // [64][3] flat

    const int tid = threadIdx.x;
    const int lane = tid & 31;
    const int warp = tid >> 5;
    const int row0 = blockIdx.x * 64;
    const int m0 = warp * 16;

    // load quantum tables + epilogue constants into smem (visibility via prologue sync)
    for (int i = tid; i < 4096; i += 128) sGr[i] = ((const float*)g_Gr)[i];
    for (int i = tid; i < 4096; i += 128) sGi[i] = ((const float*)g_Gi)[i];
    for (int i = tid; i < 192; i += 128) sG[i] = ((const float*)g_G)[i];
    for (int i = tid; i < 192; i += 128) sWf[i] = Wf[(i >> 6) * 80 + (i & 63)];
    if (tid < 64) sB1[tid] = b1[tid];
    if (tid < 3) sd[tid] = g_d[tid];

    // loader coords: 512 float4 per matrix per chunk, 4 per thread
    int lrow[4], lk[4];
    #pragma unroll
    for (int g = 0; g < 4; g++) {
        int f = g * 128 + tid;
        lrow[g] = f >> 3;
        lk[g] = (f & 7) * 4;
    }

    float4 pa[4], pb[4];
    float acc[8][4];
    #pragma unroll
    for (int nt = 0; nt < 8; nt++)
        #pragma unroll
        for (int e = 0; e < 4; e++) acc[nt][e] = 0.f;

    const u32 arow = (u32)(m0 + (lane & 7) + ((lane >> 3) & 1) * 8);
    const u32 akof = (u32)((lane >> 4) * 8);
    const u32 brow_base = (u32)((lane & 7) + (lane >> 4) * 8);
    const u32 bkof = (u32)(((lane >> 3) & 1) * 8);

#define LOAD_CHUNK(kc) do { \
    _Pragma("unroll") \
    for (int g = 0; g < 4; g++) { \
        pa[g] = *(const float4*)(xc + (size_t)(row0 + lrow[g]) * 2048 + (kc) + lk[g]); \
        pb[g] = *(const float4*)(W1 + (size_t)lrow[g] * 2048 + (kc) + lk[g]); \
    } } while (0)

#define STORE_CHUNK(bufb) do { \
    _Pragma("unroll") \
    for (int g = 0; g < 4; g++) { \
        u32 o = aoff((u32)lrow[g], (u32)lk[g]); \
        split4((bufb) + BUF_A_HI + o, (bufb) + BUF_A_LO + o, pa[g]); \
        split4((bufb) + BUF_B_HI + o, (bufb) + BUF_B_LO + o, pb[g]); \
    } } while (0)

    LOAD_CHUNK(0);
    STORE_CHUNK(ring);
    LOAD_CHUNK(KC);
    STORE_CHUNK(ring + BUFSZ);
    LOAD_CHUNK(2 * KC);
    __syncthreads();

    #pragma unroll 1
    for (int i = 0; i < NCHUNK; i++) {
        if (i + 2 < NCHUNK) {
            STORE_CHUNK(ring + ((i + 2) % 3) * BUFSZ);
        }
        if (i + 3 < NCHUNK) {
            LOAD_CHUNK((i + 3) * KC);
        }
        const u32 bb = ring + (i % 3) * BUFSZ;
        #pragma unroll
        for (int ks = 0; ks < 2; ks++) {
            u32 ah[4], al[4];
            u32 aaddr = aoff(arow, (u32)(ks * 16) + akof);
            LDMX4(ah[0], ah[1], ah[2], ah[3], bb + BUF_A_HI + aaddr);
            LDMX4(al[0], al[1], al[2], al[3], bb + BUF_A_LO + aaddr);
            u32 bh[16], bl[16];
            #pragma unroll
            for (int g = 0; g < 4; g++) {
                u32 baddr = aoff((u32)(g * 16) + brow_base, (u32)(ks * 16) + bkof);
                LDMX4(bh[4 * g], bh[4 * g + 1], bh[4 * g + 2], bh[4 * g + 3], bb + BUF_B_HI + baddr);
                LDMX4(bl[4 * g], bl[4 * g + 1], bl[4 * g + 2], bl[4 * g + 3], bb + BUF_B_LO + baddr);
            }
            #pragma unroll
            for (int nt = 0; nt < 8; nt++) {
                MMA16816(acc[nt], ah, bh[2 * nt], bh[2 * nt + 1]);
                MMA16816(acc[nt], ah, bl[2 * nt], bl[2 * nt + 1]);
                MMA16816(acc[nt], al, bh[2 * nt], bh[2 * nt + 1]);
            }
        }
        __syncthreads();
    }

    // ---- gemm partial: relu(acc + b1) . Wf, reduce over 4-lane column group ----
    float o[2][3] = {{0.f, 0.f, 0.f}, {0.f, 0.f, 0.f}};
    #pragma unroll
    for (int nt = 0; nt < 8; nt++) {
        const int n0 = nt * 8 + 2 * (lane & 3);
        const int n1 = n0 + 1;
        const float bb0 = sB1[n0], bb1 = sB1[n1];
        float c00 = acc[nt][0] + bb0; c00 = c00 > 0.f ? c00 : 0.f;
        float c01 = acc[nt][1] + bb1; c01 = c01 > 0.f ? c01 : 0.f;
        float c10 = acc[nt][2] + bb0; c10 = c10 > 0.f ? c10 : 0.f;
        float c11 = acc[nt][3] + bb1; c11 = c11 > 0.f ? c11 : 0.f;
        #pragma unroll
        for (int j = 0; j < 3; j++) {
            o[0][j] += c00 * sWf[j * 64 + n0] + c01 * sWf[j * 64 + n1];
            o[1][j] += c10 * sWf[j * 64 + n0] + c11 * sWf[j * 64 + n1];
        }
    }
    #pragma unroll
    for (int r = 0; r < 2; r++)
        #pragma unroll
        for (int j = 0; j < 3; j++) {
            o[r][j] += __shfl_xor_sync(0xFFFFFFFFu, o[r][j], 1);
            o[r][j] += __shfl_xor_sync(0xFFFFFFFFu, o[r][j], 2);
        }

    // ---- quantum part: 2 threads per sample, s-range split ----
    {
        const int sl = tid >> 1;
        const int half = tid & 1;
        const int sample = row0 + sl;
        float csq[NQ], snq[NQ];
        #pragma unroll
        for (int q = 0; q < NQ; q++) sincosf(0.5f * xq[sample * NQ + q], &snq[q], &csq[q]);

        float a[64];
        a[0] = csq[0]; a[1] = snq[0];
        #pragma unroll
        for (int q = 1; q < NQ; q++) {
            const int n = 1 << q;
            #pragma unroll 32
            for (int j = n - 1; j >= 0; j--) {
                float v = a[j];
                a[2 * j]     = v * csq[q];
                a[2 * j + 1] = v * snq[q];
            }
        }

        float q0 = 0.f, q1 = 0.f, q2 = 0.f;
        const int s0 = half * 32;
        #pragma unroll 2
        for (int ss = 0; ss < 32; ss++) {
            const int s = s0 + ss;
            const float4* gr = (const float4*)(sGr + s * 64);
            const float4* gi = (const float4*)(sGi + s * 64);
            float yr0 = 0.f, yr1 = 0.f, yi0 = 0.f, yi1 = 0.f;
            #pragma unroll
            for (int t4 = 0; t4 < 16; t4++) {
                float4 g1 = gr[t4], g2 = gi[t4];
                const float* av = &a[t4 * 4];
                yr0 += g1.x * av[0]; yr1 += g1.y * av[1];
                yr0 += g1.z * av[2]; yr1 += g1.w * av[3];
                yi0 += g2.x * av[0]; yi1 += g2.y * av[1];
                yi0 += g2.z * av[2]; yi1 += g2.w * av[3];
            }
            float yr = yr0 + yr1, yi = yi0 + yi1;
            float p = yr * yr + yi * yi;
            q0 += p * sG[s];
            q1 += p * sG[64 + s];
            q2 += p * sG[128 + s];
        }
        q0 += __shfl_xor_sync(0xFFFFFFFFu, q0, 1);
        q1 += __shfl_xor_sync(0xFFFFFFFFu, q1, 1);
        q2 += __shfl_xor_sync(0xFFFFFFFFu, q2, 1);
        if (half == 0) {
            sQ[sl * 3 + 0] = q0 + sd[0];
            sQ[sl * 3 + 1] = q1 + sd[1];
            sQ[sl * 3 + 2] = q2 + sd[2];
        }
    }
    __syncthreads();

    if ((lane & 3) == 0) {
        const int lr0 = m0 + (lane >> 2);
        const int gr0 = row0 + lr0;
        #pragma unroll
        for (int j = 0; j < 3; j++) {
            out[(size_t)gr0 * 3 + j]       = o[0][j] + sQ[lr0 * 3 + j];
            out[(size_t)(gr0 + 8) * 3 + j] = o[1][j] + sQ[(lr0 + 8) * 3 + j];
        }
    }
}

// ==================== launch ====================
extern "C" void kernel_launch(void* const* d_in, const int* in_sizes, int n_in,
                              void* d_out, int out_size) {
    const float* xc = (const float*)d_in[0];
    const float* xq = (const float*)d_in[1];
    const float* W1 = (const float*)d_in[2];
    const float* b1 = (const float*)d_in[3];
    const float* qw = (const float*)d_in[4];
    const float* Wq = (const float*)d_in[5];
    const float* bq = (const float*)d_in[6];
    const float* Wf = (const float*)d_in[7];
    const float* bf = (const float*)d_in[8];
    float* out = (float*)d_out;

    const int B = in_sizes[0] / 2048;  // 16384

    static int configured = 0;
    if (!configured) {
        cudaFuncSetAttribute(fused_kernel, cudaFuncAttributeMaxDynamicSharedMemorySize, GEMM_DSMEM);
        configured = 1;
    }

    precompute_kernel<<<4, 256>>>(qw, Wq, bq, Wf, bf);
    fused_kernel<<<B / 64, 128, GEMM_DSMEM>>>(xc, W1, b1, Wf, xq, out);
}